// round 3
// baseline (speedup 1.0000x reference)
#include <cuda_runtime.h>
#include <math_constants.h>

// Problem constants (fixed by reference setup_inputs)
#define B_   8
#define C_   24
#define H_   320
#define W_   640
#define HW_  (H_ * W_)          // 204800
#define NPIX (B_ * HW_)         // 1638400

// Each thread processes 4 consecutive pixels (one float4 along W).
__global__ __launch_bounds__(256) void sparse_regression_kernel(
    const float* __restrict__ cost,
    const float* __restrict__ disp,
    float* __restrict__ out)
{
    const int t = blockIdx.x * blockDim.x + threadIdx.x;
    const int p = t * 4;                     // first pixel of this thread's group
    if (p >= NPIX) return;

    const int b  = p / HW_;
    const int hw = p - b * HW_;
    const size_t base = (size_t)b * (C_ * HW_) + hw;   // &cost[b][0][hw]

    // Running top-2 per lane (4 lanes = 4 pixels)
    float v1[4], v2[4];
    int   i1[4], i2[4];

    // c = 0 initializes
    {
        const float4 cv = __ldg((const float4*)(cost + base));
        const float c0[4] = {cv.x, cv.y, cv.z, cv.w};
#pragma unroll
        for (int j = 0; j < 4; ++j) {
            v1[j] = c0[j]; i1[j] = 0;
            v2[j] = -CUDART_INF_F; i2[j] = 0;
        }
    }

#pragma unroll
    for (int c = 1; c < C_; ++c) {
        const float4 cv = __ldg((const float4*)(cost + base + (size_t)c * HW_));
        const float cc[4] = {cv.x, cv.y, cv.z, cv.w};
#pragma unroll
        for (int j = 0; j < 4; ++j) {
            const float v = cc[j];
            if (v > v1[j]) {
                v2[j] = v1[j]; i2[j] = i1[j];
                v1[j] = v;     i1[j] = c;
            } else if (v > v2[j]) {
                v2[j] = v;     i2[j] = c;
            }
        }
    }

    // Gather the two winning disparities per pixel (8 scalar loads)
    float d1[4], d2[4];
#pragma unroll
    for (int j = 0; j < 4; ++j) {
        d1[j] = __ldg(disp + base + (size_t)i1[j] * HW_ + j);
        d2[j] = __ldg(disp + base + (size_t)i2[j] * HW_ + j);
    }

    // Softmax over the two top costs + weighted sum
    float4 pred, pr1, pr2;
    float pj1[4], pj2[4], pd[4];
#pragma unroll
    for (int j = 0; j < 4; ++j) {
        const float e   = __expf(v2[j] - v1[j]);   // <= 1, no overflow
        const float inv = 1.0f / (1.0f + e);
        pj1[j] = inv;
        pj2[j] = e * inv;
        pd[j]  = d1[j] * pj1[j] + d2[j] * pj2[j];
    }
    pred = make_float4(pd[0],  pd[1],  pd[2],  pd[3]);
    pr1  = make_float4(pj1[0], pj1[1], pj1[2], pj1[3]);
    pr2  = make_float4(pj2[0], pj2[1], pj2[2], pj2[3]);

    // Output layout: pred [B,H,W] (NPIX floats) then prob [B,2,H,W]
    *(float4*)(out + p) = pred;
    float* prob = out + NPIX;
    const size_t pb = (size_t)b * (2 * HW_) + hw;
    *(float4*)(prob + pb)        = pr1;   // k = 0 (largest)
    *(float4*)(prob + pb + HW_)  = pr2;   // k = 1
}

extern "C" void kernel_launch(void* const* d_in, const int* in_sizes, int n_in,
                              void* d_out, int out_size)
{
    const float* cost = (const float*)d_in[0];
    const float* disp = (const float*)d_in[1];
    float* out = (float*)d_out;

    const int threads = 256;
    const int total   = NPIX / 4;                    // 409600 threads
    const int blocks  = (total + threads - 1) / threads;
    sparse_regression_kernel<<<blocks, threads>>>(cost, disp, out);
}

// round 4
// speedup vs baseline: 1.1649x; 1.1649x over previous
#include <cuda_runtime.h>
#include <math_constants.h>

// Problem constants (fixed by reference setup_inputs)
#define B_   8
#define C_   24
#define H_   320
#define W_   640
#define HW_  (H_ * W_)          // 204800
#define NPIX (B_ * HW_)         // 1638400

// Each thread processes 4 consecutive pixels (one float4 along W).
// Pure streaming: cost AND disparity are both read sequentially; the top-2
// disparity values are carried in registers so no random gather is needed.
__global__ __launch_bounds__(256) void sparse_regression_kernel(
    const float* __restrict__ cost,
    const float* __restrict__ disp,
    float* __restrict__ out)
{
    const int t = blockIdx.x * blockDim.x + threadIdx.x;
    const int p = t * 4;                     // first pixel of this thread's group
    if (p >= NPIX) return;

    const int b  = p / HW_;
    const int hw = p - b * HW_;
    const size_t base = (size_t)b * (C_ * HW_) + hw;   // &cost[b][0][hw]

    // Running top-2 (value + disparity) per lane (4 lanes = 4 pixels)
    float v1[4], v2[4], d1[4], d2[4];

    // c = 0 initializes
    {
        const float4 cv = __ldcs((const float4*)(cost + base));
        const float4 dv = __ldcs((const float4*)(disp + base));
        const float cc[4] = {cv.x, cv.y, cv.z, cv.w};
        const float dd[4] = {dv.x, dv.y, dv.z, dv.w};
#pragma unroll
        for (int j = 0; j < 4; ++j) {
            v1[j] = cc[j];          d1[j] = dd[j];
            v2[j] = -CUDART_INF_F;  d2[j] = 0.0f;
        }
    }

#pragma unroll
    for (int c = 1; c < C_; ++c) {
        const float4 cv = __ldcs((const float4*)(cost + base + (size_t)c * HW_));
        const float4 dv = __ldcs((const float4*)(disp + base + (size_t)c * HW_));
        const float cc[4] = {cv.x, cv.y, cv.z, cv.w};
        const float dd[4] = {dv.x, dv.y, dv.z, dv.w};
#pragma unroll
        for (int j = 0; j < 4; ++j) {
            const float v  = cc[j];
            const float dI = dd[j];
            const bool gt1 = v > v1[j];
            const bool gt2 = v > v2[j];
            // second place: displaced old-first, or the new value, or unchanged
            v2[j] = gt1 ? v1[j] : (gt2 ? v  : v2[j]);
            d2[j] = gt1 ? d1[j] : (gt2 ? dI : d2[j]);
            // first place
            v1[j] = gt1 ? v  : v1[j];
            d1[j] = gt1 ? dI : d1[j];
        }
    }

    // Softmax over the two top costs + weighted sum
    float pj1[4], pj2[4], pd[4];
#pragma unroll
    for (int j = 0; j < 4; ++j) {
        const float e   = __expf(v2[j] - v1[j]);   // <= 1, no overflow
        const float inv = 1.0f / (1.0f + e);
        pj1[j] = inv;
        pj2[j] = e * inv;
        pd[j]  = d1[j] * pj1[j] + d2[j] * pj2[j];
    }

    // Output layout: pred [B,H,W] (NPIX floats) then prob [B,2,H,W]
    *(float4*)(out + p) = make_float4(pd[0], pd[1], pd[2], pd[3]);
    float* prob = out + NPIX;
    const size_t pb = (size_t)b * (2 * HW_) + hw;
    *(float4*)(prob + pb)       = make_float4(pj1[0], pj1[1], pj1[2], pj1[3]); // k=0
    *(float4*)(prob + pb + HW_) = make_float4(pj2[0], pj2[1], pj2[2], pj2[3]); // k=1
}

extern "C" void kernel_launch(void* const* d_in, const int* in_sizes, int n_in,
                              void* d_out, int out_size)
{
    const float* cost = (const float*)d_in[0];
    const float* disp = (const float*)d_in[1];
    float* out = (float*)d_out;

    const int threads = 256;
    const int total   = NPIX / 4;                    // 409600 threads
    const int blocks  = (total + threads - 1) / threads;
    sparse_regression_kernel<<<blocks, threads>>>(cost, disp, out);
}